// round 3
// baseline (speedup 1.0000x reference)
#include <cuda_runtime.h>
#include <math.h>

#define B_  4
#define C_  64
#define O_  64
#define H_  128
#define W_  128
#define K2_ 9
#define OCOFF 27

// scratch: offsets/mask [b][ch=27][h][w], transposed weights
__device__ float g_off[B_ * OCOFF * H_ * W_];        // 1,769,472 floats
__device__ float g_wt [K2_ * C_ * O_];               // w_def as [k][c][o]
__device__ float g_wo [K2_ * C_ * 32];               // w_off as [k][c][o(pad32)]

// ---------------------------------------------------------------------------
// Kernel 0: transpose weights into GEMM-friendly [k][c][o] layout (tiny)
// ---------------------------------------------------------------------------
__global__ void prep_w_kernel(const float* __restrict__ w_off,
                              const float* __restrict__ w_def) {
    int i = blockIdx.x * 256 + threadIdx.x;
    if (i < K2_ * C_ * O_) {
        int k = i / (C_ * O_);
        int r = i % (C_ * O_);
        int c = r >> 6, o = r & 63;
        g_wt[i] = w_def[(o * C_ + c) * K2_ + k];
    }
    if (i < K2_ * C_ * 32) {
        int k = i / (C_ * 32);
        int r = i % (C_ * 32);
        int c = r >> 5, o = r & 31;
        g_wo[i] = (o < OCOFF) ? w_off[(o * C_ + c) * K2_ + k] : 0.f;
    }
}

// ---------------------------------------------------------------------------
// Kernel 1: offset/mask conv.  Block = (b, h, 64-px segment), 256 threads.
// Double-buffered feat tile, weights via L1-broadcast LDG, 1 sync per tap.
// Output tile: 27(32) o x 64 p.  Thread micro-tile: 2o x 4p.
// ---------------------------------------------------------------------------
__global__ __launch_bounds__(256) void offset_conv_kernel(
    const float* __restrict__ feat, const float* __restrict__ b_off) {
    int blk  = blockIdx.x;
    int wseg = blk & 1;
    int h    = (blk >> 1) & (H_ - 1);
    int b    = blk >> 8;
    int w0   = wseg * 64;
    int t    = threadIdx.x;

    __shared__ float s_x[2][C_ * 64];   // [buf][c][p]  32 KB

    const int to = t >> 4;   // 0..15 -> o base = to*2
    const int tp = t & 15;   // 0..15 -> p base = tp*4
    float acc[2][4] = {};

    const float* fb = feat + (size_t)b * C_ * H_ * W_;

    // stage tap 0
    {
        int hs = h - 1;
        for (int i = t; i < C_ * 64; i += 256) {
            int c = i >> 6, p = i & 63;
            int ws = w0 + p - 1;
            float v = 0.f;
            if (hs >= 0 && hs < H_ && ws >= 0 && ws < W_)
                v = fb[(c * H_ + hs) * W_ + ws];
            s_x[0][i] = v;
        }
    }
    __syncthreads();

    for (int k = 0; k < K2_; k++) {
        // stage tap k+1 into the other buffer (overlaps with GEMM of tap k)
        if (k + 1 < K2_) {
            int kn = k + 1;
            int dy = kn / 3 - 1, dx = kn % 3 - 1;
            int hs = h + dy;
            float* dst = s_x[kn & 1];
            for (int i = t; i < C_ * 64; i += 256) {
                int c = i >> 6, p = i & 63;
                int ws = w0 + p + dx;
                float v = 0.f;
                if (hs >= 0 && hs < H_ && ws >= 0 && ws < W_)
                    v = fb[(c * H_ + hs) * W_ + ws];
                dst[i] = v;
            }
        }
        // GEMM tap k: weights from L2/L1 via broadcast LDG
        const float* buf = s_x[k & 1];
        const float2* gw = (const float2*)(g_wo + k * (C_ * 32));
#pragma unroll 8
        for (int c = 0; c < C_; c++) {
            float4 xv = *(const float4*)&buf[c * 64 + tp * 4];
            float2 wv = __ldg(&gw[c * 16 + to]);
            acc[0][0] += wv.x * xv.x; acc[0][1] += wv.x * xv.y;
            acc[0][2] += wv.x * xv.z; acc[0][3] += wv.x * xv.w;
            acc[1][0] += wv.y * xv.x; acc[1][1] += wv.y * xv.y;
            acc[1][2] += wv.y * xv.z; acc[1][3] += wv.y * xv.w;
        }
        __syncthreads();
    }
    // epilogue: bias, sigmoid for mask channels (18..26), store to g_off
#pragma unroll
    for (int j = 0; j < 2; j++) {
        int o = to * 2 + j;
        if (o >= OCOFF) continue;
        float bb = b_off[o];
        bool is_mask = (o >= 18);
        float* dst = &g_off[((b * OCOFF + o) * H_ + h) * W_ + w0 + tp * 4];
#pragma unroll
        for (int q = 0; q < 4; q++) {
            float v = acc[j][q] + bb;
            if (is_mask) v = 1.f / (1.f + expf(-v));
            dst[q] = v;
        }
    }
}

// ---------------------------------------------------------------------------
// Kernel 2: fused deformable sampling + 64x576 contraction + bias + relu.
// Block = (b, h, 64-px segment), 256 threads.
//   prologue: all 9 taps' gather indices + mask-folded bilinear weights
//   per tap:  sample tap k+1 into buf[(k+1)&1]  ||  GEMM tap k from buf[k&1]
//             weights via L1-broadcast LDG; exactly one __syncthreads per tap
// Thread micro-tile: 4o x 4p.
// ---------------------------------------------------------------------------
__global__ __launch_bounds__(256) void deform_gemm_kernel(
    const float* __restrict__ x, const float* __restrict__ b_def,
    float* __restrict__ out) {
    int blk  = blockIdx.x;
    int wseg = blk & 1;
    int h    = (blk >> 1) & (H_ - 1);
    int b    = blk >> 8;
    int w0   = wseg * 64;
    int t    = threadIdx.x;

    __shared__ float s_cols[2][C_ * 64];   // 32 KB
    __shared__ int   s_idx [K2_][64 * 4];  // 9 KB  per-pixel 4 corner indices
    __shared__ float s_wtc [K2_][64 * 4];  // 9 KB  per-pixel 4 corner weights*mask

    const int to = t >> 4;   // o base = to*4
    const int tp = t & 15;   // p base = tp*4
    float acc[4][4] = {};
    const float* xb = x + (size_t)b * C_ * H_ * W_;

    const int sp = t & 63;   // sampling pixel
    const int sc = t >> 6;   // sampling channel base (0..3)

    // ---- prologue: precompute gather idx/weights for ALL taps ----
    for (int e = t; e < K2_ * 64; e += 256) {
        int k = e >> 6;
        int p = e & 63;
        int dy = k / 3 - 1, dx = k % 3 - 1;
        int base = (b * OCOFF * H_ + h) * W_ + (w0 + p);
        float ox = g_off[base + (0 * 9 + k) * (H_ * W_)];
        float oy = g_off[base + (1 * 9 + k) * (H_ * W_)];
        float m  = g_off[base + (2 * 9 + k) * (H_ * W_)];
        float ys = (float)(h + dy) + oy;
        float xs = (float)(w0 + p + dx) + ox;
        float y0f = floorf(ys), x0f = floorf(xs);
        float wy1 = ys - y0f, wx1 = xs - x0f;
        int y0 = (int)y0f, x0 = (int)x0f;
#pragma unroll
        for (int cr = 0; cr < 4; cr++) {
            int oyc = cr >> 1, oxc = cr & 1;
            int yy = y0 + oyc, xx = x0 + oxc;
            float wgt = (oyc ? wy1 : 1.f - wy1) * (oxc ? wx1 : 1.f - wx1) * m;
            bool valid = (yy >= 0) & (yy < H_) & (xx >= 0) & (xx < W_);
            int yc = min(max(yy, 0), H_ - 1);
            int xc = min(max(xx, 0), W_ - 1);
            s_idx[k][p * 4 + cr] = yc * W_ + xc;
            s_wtc[k][p * 4 + cr] = valid ? wgt : 0.f;
        }
    }
    __syncthreads();

    // ---- sample tap 0 ----
    {
        int4   iv = *(const int4*)  &s_idx[0][sp * 4];
        float4 wv = *(const float4*)&s_wtc[0][sp * 4];
#pragma unroll
        for (int j = 0; j < 16; j++) {
            int c = sc + j * 4;
            const float* xc = xb + c * (H_ * W_);
            s_cols[0][c * 64 + sp] = wv.x * xc[iv.x] + wv.y * xc[iv.y] +
                                     wv.z * xc[iv.z] + wv.w * xc[iv.w];
        }
    }
    __syncthreads();

    for (int k = 0; k < K2_; k++) {
        // sample tap k+1 into the other buffer (overlaps GEMM of tap k)
        if (k + 1 < K2_) {
            int kn = k + 1;
            float* buf = s_cols[kn & 1];
            int4   iv = *(const int4*)  &s_idx[kn][sp * 4];
            float4 wv = *(const float4*)&s_wtc[kn][sp * 4];
#pragma unroll
            for (int j = 0; j < 16; j++) {
                int c = sc + j * 4;
                const float* xc = xb + c * (H_ * W_);
                buf[c * 64 + sp] = wv.x * xc[iv.x] + wv.y * xc[iv.y] +
                                   wv.z * xc[iv.z] + wv.w * xc[iv.w];
            }
        }
        // GEMM tap k: acc[o][p] += w[c][o] * cols[c][p]
        const float*  buf = s_cols[k & 1];
        const float4* gw  = (const float4*)(g_wt + k * (C_ * O_));
#pragma unroll 4
        for (int c = 0; c < C_; c++) {
            float4 xv = *(const float4*)&buf[c * 64 + tp * 4];
            float4 wv = __ldg(&gw[c * 16 + to]);
            acc[0][0] += wv.x * xv.x; acc[0][1] += wv.x * xv.y;
            acc[0][2] += wv.x * xv.z; acc[0][3] += wv.x * xv.w;
            acc[1][0] += wv.y * xv.x; acc[1][1] += wv.y * xv.y;
            acc[1][2] += wv.y * xv.z; acc[1][3] += wv.y * xv.w;
            acc[2][0] += wv.z * xv.x; acc[2][1] += wv.z * xv.y;
            acc[2][2] += wv.z * xv.z; acc[2][3] += wv.z * xv.w;
            acc[3][0] += wv.w * xv.x; acc[3][1] += wv.w * xv.y;
            acc[3][2] += wv.w * xv.z; acc[3][3] += wv.w * xv.w;
        }
        __syncthreads();
    }
    // ---- epilogue: bias + relu, vectorized store ----
#pragma unroll
    for (int j = 0; j < 4; j++) {
        int o = to * 4 + j;
        float bb = b_def[o];
        float4 r;
        r.x = fmaxf(acc[j][0] + bb, 0.f);
        r.y = fmaxf(acc[j][1] + bb, 0.f);
        r.z = fmaxf(acc[j][2] + bb, 0.f);
        r.w = fmaxf(acc[j][3] + bb, 0.f);
        *(float4*)&out[((b * O_ + o) * H_ + h) * W_ + w0 + tp * 4] = r;
    }
}

// ---------------------------------------------------------------------------
extern "C" void kernel_launch(void* const* d_in, const int* in_sizes, int n_in,
                              void* d_out, int out_size) {
    const float* x     = (const float*)d_in[0];
    const float* feat  = (const float*)d_in[1];
    const float* w_off = (const float*)d_in[2];
    const float* b_off = (const float*)d_in[3];
    const float* w_def = (const float*)d_in[4];
    const float* b_def = (const float*)d_in[5];
    float* out = (float*)d_out;

    prep_w_kernel<<<(K2_ * C_ * O_ + 255) / 256, 256>>>(w_off, w_def);
    offset_conv_kernel<<<B_ * H_ * (W_ / 64), 256>>>(feat, b_off);
    deform_gemm_kernel<<<B_ * H_ * (W_ / 64), 256>>>(x, b_def, out);
}

// round 4
// speedup vs baseline: 1.2438x; 1.2438x over previous
#include <cuda_runtime.h>
#include <math.h>

#define B_  4
#define C_  64
#define O_  64
#define H_  128
#define W_  128
#define K2_ 9
#define OCOFF 27
#define HW_ (H_ * W_)

// scratch: offsets/mask [b][ch=27][h][w], transposed weights
__device__ float g_off[B_ * OCOFF * HW_];
__device__ float g_wt [K2_ * C_ * O_];      // w_def as [k][c][o]
__device__ float g_wo [K2_ * C_ * 32];      // w_off as [k][c][o(pad32)]

// ---------------------------------------------------------------------------
// packed fp32 helpers (FFMA2 — exact fp32, 2 lanes per instr, sm_100+)
// ---------------------------------------------------------------------------
__device__ __forceinline__ unsigned long long dupf(float v) {
    unsigned long long r;
    asm("mov.b64 %0, {%1, %1};" : "=l"(r) : "f"(v));
    return r;
}
__device__ __forceinline__ void fma2(unsigned long long& a,
                                     unsigned long long w,
                                     unsigned long long x) {
    asm("fma.rn.f32x2 %0, %1, %2, %0;" : "+l"(a) : "l"(w), "l"(x));
}
__device__ __forceinline__ void unpack2(unsigned long long v, float& lo, float& hi) {
    asm("mov.b64 {%0, %1}, %2;" : "=f"(lo), "=f"(hi) : "l"(v));
}

// ---------------------------------------------------------------------------
// Kernel 0: transpose weights into GEMM-friendly [k][c][o] layout (tiny)
// ---------------------------------------------------------------------------
__global__ void prep_w_kernel(const float* __restrict__ w_off,
                              const float* __restrict__ w_def) {
    int i = blockIdx.x * 256 + threadIdx.x;
    if (i < K2_ * C_ * O_) {
        int k = i / (C_ * O_);
        int r = i % (C_ * O_);
        int c = r >> 6, o = r & 63;
        g_wt[i] = w_def[(o * C_ + c) * K2_ + k];
    }
    if (i < K2_ * C_ * 32) {
        int k = i / (C_ * 32);
        int r = i % (C_ * 32);
        int c = r >> 5, o = r & 31;
        g_wo[i] = (o < OCOFF) ? w_off[(o * C_ + c) * K2_ + k] : 0.f;
    }
}

// ---------------------------------------------------------------------------
// Kernel 1: offset/mask conv.  Block = (b, h, 64-px segment), 256 threads.
// Double-buffered feat tile AND weight tile in smem; chunk-interleaved
// staging/GEMM; exactly one __syncthreads per tap.
// Output tile: 27(32) o x 64 p.  Thread micro-tile: 2o x 4p.
// ---------------------------------------------------------------------------
__global__ __launch_bounds__(256) void offset_conv_kernel(
    const float* __restrict__ feat, const float* __restrict__ b_off) {
    int blk  = blockIdx.x;
    int wseg = blk & 1;
    int h    = (blk >> 1) & (H_ - 1);
    int b    = blk >> 8;
    int w0   = wseg * 64;
    int t    = threadIdx.x;

    __shared__ float s_x[2][C_ * 64];   // 32 KB
    __shared__ float s_w[2][C_ * 32];   // 16 KB

    const int to = t >> 4;   // o base = to*2
    const int tp = t & 15;   // p base = tp*4
    float acc[2][4] = {};

    const float* fb = feat + (size_t)b * C_ * HW_;

    // prologue: stage tap 0 (x + w)
    {
        int hs = h - 1;
        for (int i = t; i < C_ * 64; i += 256) {
            int c = i >> 6, p = i & 63;
            int ws = w0 + p - 1;
            float v = 0.f;
            if (hs >= 0 && ws >= 0 && ws < W_)
                v = fb[(c * H_ + hs) * W_ + ws];
            s_x[0][i] = v;
        }
        for (int i = t; i < C_ * 32 / 4; i += 256)
            ((float4*)s_w[0])[i] = ((const float4*)g_wo)[i];
    }
    __syncthreads();

    for (int k = 0; k < K2_; k++) {
        int kn = k + 1;
        int dy = kn / 3 - 1, dx = kn % 3 - 1;
        int hs = h + dy;
        const float* bx = s_x[k & 1];
        const float* bw = s_w[k & 1];
        float* nx = s_x[kn & 1];
        float* nw = s_w[kn & 1];

#pragma unroll
        for (int chunk = 0; chunk < 4; chunk++) {
            if (kn < K2_) {
                // stage quarter of next feat tile
#pragma unroll
                for (int q = 0; q < 4; q++) {
                    int i = chunk * 1024 + q * 256 + t;
                    int c = i >> 6, p = i & 63;
                    int ws = w0 + p + dx;
                    float v = 0.f;
                    if (hs >= 0 && hs < H_ && ws >= 0 && ws < W_)
                        v = fb[(c * H_ + hs) * W_ + ws];
                    nx[i] = v;
                }
                // stage next weight tile (512 float4 total -> chunks 0,1)
                if (chunk < 2)
                    ((float4*)nw)[chunk * 256 + t] =
                        ((const float4*)(g_wo + kn * (C_ * 32)))[chunk * 256 + t];
            }
            // GEMM: 16 channels of tap k
#pragma unroll
            for (int cc = 0; cc < 16; cc++) {
                int c = chunk * 16 + cc;
                float4 xv = *(const float4*)&bx[c * 64 + tp * 4];
                float2 wv = *(const float2*)&bw[c * 32 + to * 2];
                acc[0][0] += wv.x * xv.x; acc[0][1] += wv.x * xv.y;
                acc[0][2] += wv.x * xv.z; acc[0][3] += wv.x * xv.w;
                acc[1][0] += wv.y * xv.x; acc[1][1] += wv.y * xv.y;
                acc[1][2] += wv.y * xv.z; acc[1][3] += wv.y * xv.w;
            }
        }
        __syncthreads();
    }
    // epilogue: bias, sigmoid for mask channels (18..26), store to g_off
#pragma unroll
    for (int j = 0; j < 2; j++) {
        int o = to * 2 + j;
        if (o >= OCOFF) continue;
        float bb = b_off[o];
        bool is_mask = (o >= 18);
        float* dst = &g_off[((b * OCOFF + o) * H_ + h) * W_ + w0 + tp * 4];
#pragma unroll
        for (int q = 0; q < 4; q++) {
            float v = acc[j][q] + bb;
            if (is_mask) v = 1.f / (1.f + expf(-v));
            dst[q] = v;
        }
    }
}

// ---------------------------------------------------------------------------
// per-thread bilinear gather setup for one tap (registers only)
// ---------------------------------------------------------------------------
__device__ __forceinline__ void comp_idx(int k, int b, int h, int w0, int sp,
                                         int iv[4], float wf[4]) {
    int dy = k / 3 - 1, dx = k % 3 - 1;
    int base = (b * OCOFF * H_ + h) * W_ + (w0 + sp);
    float ox = g_off[base + (0 * 9 + k) * HW_];
    float oy = g_off[base + (1 * 9 + k) * HW_];
    float m  = g_off[base + (2 * 9 + k) * HW_];
    float ys = (float)(h + dy) + oy;
    float xs = (float)(w0 + sp + dx) + ox;
    float y0f = floorf(ys), x0f = floorf(xs);
    float wy1 = ys - y0f, wx1 = xs - x0f;
    int y0 = (int)y0f, x0 = (int)x0f;
#pragma unroll
    for (int cr = 0; cr < 4; cr++) {
        int oyc = cr >> 1, oxc = cr & 1;
        int yy = y0 + oyc, xx = x0 + oxc;
        float wgt = (oyc ? wy1 : 1.f - wy1) * (oxc ? wx1 : 1.f - wx1) * m;
        bool valid = (yy >= 0) & (yy < H_) & (xx >= 0) & (xx < W_);
        int yc = min(max(yy, 0), H_ - 1);
        int xc = min(max(xx, 0), W_ - 1);
        iv[cr] = yc * W_ + xc;
        wf[cr] = valid ? wgt : 0.f;
    }
}

// ---------------------------------------------------------------------------
// Kernel 2: fused deformable sampling + 64x576 contraction + bias + relu.
// Block = (b, h, 64-px segment), 256 threads.
// Double-buffered cols AND weight tiles; gather idx/weights in registers;
// sampling + weight staging of tap k+1 chunk-interleaved with FFMA2 GEMM of
// tap k; one __syncthreads per tap.  Thread micro-tile: 4o x 4p (f32x2 pairs).
// ---------------------------------------------------------------------------
__global__ __launch_bounds__(256) void deform_gemm_kernel(
    const float* __restrict__ x, const float* __restrict__ b_def,
    float* __restrict__ out) {
    int blk  = blockIdx.x;
    int wseg = blk & 1;
    int h    = (blk >> 1) & (H_ - 1);
    int b    = blk >> 8;
    int w0   = wseg * 64;
    int t    = threadIdx.x;

    __shared__ float s_cols[2][C_ * 64];   // 32 KB
    __shared__ float s_w   [2][C_ * O_];   // 32 KB

    const int to = t >> 4;   // o base = to*4
    const int tp = t & 15;   // p base = tp*4
    const int sp = t & 63;   // sampling pixel
    const int sc = t >> 6;   // sampling channel base (0..3)

    unsigned long long acc[4][2] = {};     // [o][p-pair], packed fp32x2
    const float* xb = x + (size_t)b * C_ * HW_;

    // prologue: stage w tap 0 + sample tap 0
    for (int i = t; i < C_ * O_ / 4; i += 256)
        ((float4*)s_w[0])[i] = ((const float4*)g_wt)[i];
    {
        int iv[4]; float wf[4];
        comp_idx(0, b, h, w0, sp, iv, wf);
#pragma unroll
        for (int j = 0; j < 16; j++) {
            int c = sc + j * 4;
            const float* xc = xb + c * HW_;
            s_cols[0][c * 64 + sp] = wf[0] * xc[iv[0]] + wf[1] * xc[iv[1]] +
                                     wf[2] * xc[iv[2]] + wf[3] * xc[iv[3]];
        }
    }
    __syncthreads();

    for (int k = 0; k < K2_; k++) {
        int kn = k + 1;
        int iv[4]; float wf[4];
        if (kn < K2_) comp_idx(kn, b, h, w0, sp, iv, wf);

        const float* bc = s_cols[k & 1];
        const float* bw = s_w[k & 1];
        float* nc = s_cols[kn & 1];
        float* nw = s_w[kn & 1];

#pragma unroll
        for (int chunk = 0; chunk < 4; chunk++) {
            if (kn < K2_) {
                // sample 4 channel-groups of tap k+1 (bounded outstanding LDGs)
#pragma unroll
                for (int jj = 0; jj < 4; jj++) {
                    int c = sc + (chunk * 4 + jj) * 4;
                    const float* xc = xb + c * HW_;
                    nc[c * 64 + sp] = wf[0] * xc[iv[0]] + wf[1] * xc[iv[1]] +
                                      wf[2] * xc[iv[2]] + wf[3] * xc[iv[3]];
                }
                // stage quarter of next weight tile (vectorized)
                ((float4*)nw)[chunk * 256 + t] =
                    ((const float4*)(g_wt + kn * (C_ * O_)))[chunk * 256 + t];
            }
            // FFMA2 GEMM: 16 channels of tap k
#pragma unroll
            for (int cc = 0; cc < 16; cc++) {
                int c = chunk * 16 + cc;
                ulonglong2 xv = *(const ulonglong2*)&bc[c * 64 + tp * 4];
                float4 wv = *(const float4*)&bw[c * 64 + to * 4];
                unsigned long long w0d = dupf(wv.x);
                unsigned long long w1d = dupf(wv.y);
                unsigned long long w2d = dupf(wv.z);
                unsigned long long w3d = dupf(wv.w);
                fma2(acc[0][0], w0d, xv.x); fma2(acc[0][1], w0d, xv.y);
                fma2(acc[1][0], w1d, xv.x); fma2(acc[1][1], w1d, xv.y);
                fma2(acc[2][0], w2d, xv.x); fma2(acc[2][1], w2d, xv.y);
                fma2(acc[3][0], w3d, xv.x); fma2(acc[3][1], w3d, xv.y);
            }
        }
        __syncthreads();
    }

    // epilogue: unpack pairs, bias + relu, vectorized store
#pragma unroll
    for (int j = 0; j < 4; j++) {
        int o = to * 4 + j;
        float bb = b_def[o];
        float lo0, hi0, lo1, hi1;
        unpack2(acc[j][0], lo0, hi0);
        unpack2(acc[j][1], lo1, hi1);
        float4 r;
        r.x = fmaxf(lo0 + bb, 0.f);
        r.y = fmaxf(hi0 + bb, 0.f);
        r.z = fmaxf(lo1 + bb, 0.f);
        r.w = fmaxf(hi1 + bb, 0.f);
        *(float4*)&out[((b * O_ + o) * H_ + h) * W_ + w0 + tp * 4] = r;
    }
}

// ---------------------------------------------------------------------------
extern "C" void kernel_launch(void* const* d_in, const int* in_sizes, int n_in,
                              void* d_out, int out_size) {
    const float* x     = (const float*)d_in[0];
    const float* feat  = (const float*)d_in[1];
    const float* w_off = (const float*)d_in[2];
    const float* b_off = (const float*)d_in[3];
    const float* w_def = (const float*)d_in[4];
    const float* b_def = (const float*)d_in[5];
    float* out = (float*)d_out;

    prep_w_kernel<<<(K2_ * C_ * O_ + 255) / 256, 256>>>(w_off, w_def);
    offset_conv_kernel<<<B_ * H_ * (W_ / 64), 256>>>(feat, b_off);
    deform_gemm_kernel<<<B_ * H_ * (W_ / 64), 256>>>(x, b_def, out);
}

// round 11
// speedup vs baseline: 1.6347x; 1.3143x over previous
#include <cuda_runtime.h>
#include <cuda_bf16.h>
#include <math.h>
#include <cstdint>

#define B_  4
#define C_  64
#define O_  64
#define H_  128
#define W_  128
#define K2_ 9
#define OCOFF 27
#define HW_ (H_ * W_)

#define SWZ(a) ((a) ^ (((a) >> 3) & 0x70))

// scratch
__device__ float g_off[B_ * OCOFF * HW_];            // offsets/mask [b][27][h][w]
__device__ float g_wo [K2_ * C_ * 32];               // w_off as [k][c][o(pad32)]
__device__ __nv_bfloat16 g_wbh[K2_ * O_ * C_];       // w_def hi, [k] tiles [o][c] SW128-swizzled
__device__ __nv_bfloat16 g_wbl[K2_ * O_ * C_];       // w_def lo

// ===========================================================================
// non-'a' tensor path: ldmatrix + mma.sync (available on plain compute_103)
// ===========================================================================
__device__ __forceinline__ uint32_t smem_to_u32(const void* smem_ptr) {
    uint32_t addr;
    asm("{ .reg .u64 tmp; cvta.to.shared.u64 tmp, %1; cvt.u32.u64 %0, tmp; }"
        : "=r"(addr) : "l"(smem_ptr));
    return addr;
}

#define LDSM_X4(r, addr) \
    asm volatile("ldmatrix.sync.aligned.m8n8.x4.shared.b16 {%0,%1,%2,%3}, [%4];" \
        : "=r"((r)[0]), "=r"((r)[1]), "=r"((r)[2]), "=r"((r)[3]) \
        : "r"(addr))

#define MMA_BF16(d, a, b0, b1) \
    asm volatile("mma.sync.aligned.m16n8k16.row.col.f32.bf16.bf16.f32 " \
        "{%0,%1,%2,%3}, {%4,%5,%6,%7}, {%8,%9}, {%0,%1,%2,%3};" \
        : "+f"((d)[0]), "+f"((d)[1]), "+f"((d)[2]), "+f"((d)[3]) \
        : "r"((a)[0]), "r"((a)[1]), "r"((a)[2]), "r"((a)[3]), \
          "r"(b0), "r"(b1))

// ===========================================================================
// Kernel 0: weight prep.  g_wo for offset conv; g_wbh/g_wbl = bf16 hi/lo
// split of w_def in SW128-swizzled [k][o-row][c-col] tiles.
// ===========================================================================
__global__ void prep_w_kernel(const float* __restrict__ w_off,
                              const float* __restrict__ w_def) {
    int i = blockIdx.x * 256 + threadIdx.x;
    if (i < K2_ * O_ * C_) {
        int k = i >> 12;
        int r = i & 4095;
        int o = r >> 6;
        int c = r & 63;
        float w = w_def[(o * C_ + c) * K2_ + k];
        __nv_bfloat16 hb = __float2bfloat16(w);
        __nv_bfloat16 lb = __float2bfloat16(w - __bfloat162float(hb));
        int sw = SWZ(o * 128 + c * 2) >> 1;
        g_wbh[k * 4096 + sw] = hb;
        g_wbl[k * 4096 + sw] = lb;
    }
    if (i < K2_ * C_ * 32) {
        int k = i / (C_ * 32);
        int r = i % (C_ * 32);
        int c = r >> 5;
        int o = r & 31;
        g_wo[i] = (o < OCOFF) ? w_off[(o * C_ + c) * K2_ + k] : 0.f;
    }
}

// ===========================================================================
// Kernel 1: offset/mask conv (SIMT, double-buffered; unchanged from R4 best).
// ===========================================================================
__global__ __launch_bounds__(256) void offset_conv_kernel(
    const float* __restrict__ feat, const float* __restrict__ b_off) {
    int blk  = blockIdx.x;
    int wseg = blk & 1;
    int h    = (blk >> 1) & (H_ - 1);
    int b    = blk >> 8;
    int w0   = wseg * 64;
    int t    = threadIdx.x;

    __shared__ float s_x[2][C_ * 64];
    __shared__ float s_w[2][C_ * 32];

    const int to = t >> 4;
    const int tp = t & 15;
    float acc[2][4] = {};
    const float* fb = feat + (size_t)b * C_ * HW_;

    {
        int hs = h - 1;
        for (int i = t; i < C_ * 64; i += 256) {
            int c = i >> 6;
            int p = i & 63;
            int ws = w0 + p - 1;
            float v = 0.f;
            if (hs >= 0 && ws >= 0 && ws < W_)
                v = fb[(c * H_ + hs) * W_ + ws];
            s_x[0][i] = v;
        }
        for (int i = t; i < C_ * 32 / 4; i += 256)
            ((float4*)s_w[0])[i] = ((const float4*)g_wo)[i];
    }
    __syncthreads();

    for (int k = 0; k < K2_; k++) {
        int kn = k + 1;
        int dy = kn / 3 - 1;
        int dx = kn % 3 - 1;
        int hs = h + dy;
        const float* bx = s_x[k & 1];
        const float* bw = s_w[k & 1];
        float* nx = s_x[kn & 1];
        float* nw = s_w[kn & 1];

#pragma unroll
        for (int chunk = 0; chunk < 4; chunk++) {
            if (kn < K2_) {
#pragma unroll
                for (int q = 0; q < 4; q++) {
                    int i = chunk * 1024 + q * 256 + t;
                    int c = i >> 6;
                    int p = i & 63;
                    int ws = w0 + p + dx;
                    float v = 0.f;
                    if (hs >= 0 && hs < H_ && ws >= 0 && ws < W_)
                        v = fb[(c * H_ + hs) * W_ + ws];
                    nx[i] = v;
                }
                if (chunk < 2)
                    ((float4*)nw)[chunk * 256 + t] =
                        ((const float4*)(g_wo + kn * (C_ * 32)))[chunk * 256 + t];
            }
#pragma unroll
            for (int cc = 0; cc < 16; cc++) {
                int c = chunk * 16 + cc;
                float4 xv = *(const float4*)&bx[c * 64 + tp * 4];
                float2 wv = *(const float2*)&bw[c * 32 + to * 2];
                acc[0][0] += wv.x * xv.x; acc[0][1] += wv.x * xv.y;
                acc[0][2] += wv.x * xv.z; acc[0][3] += wv.x * xv.w;
                acc[1][0] += wv.y * xv.x; acc[1][1] += wv.y * xv.y;
                acc[1][2] += wv.y * xv.z; acc[1][3] += wv.y * xv.w;
            }
        }
        __syncthreads();
    }
#pragma unroll
    for (int j = 0; j < 2; j++) {
        int o = to * 2 + j;
        if (o < OCOFF) {
            float bb = b_off[o];
            bool is_mask = (o >= 18);
            float* dst = &g_off[((b * OCOFF + o) * H_ + h) * W_ + w0 + tp * 4];
#pragma unroll
            for (int q = 0; q < 4; q++) {
                float v = acc[j][q] + bb;
                if (is_mask) v = 1.f / (1.f + expf(-v));
                dst[q] = v;
            }
        }
    }
}

// ===========================================================================
// Kernel 2: deformable sampling (bf16 hi/lo split) + ldmatrix/mma.sync GEMM.
// Block = (b, h) -> M=128 px, N=64 o, K=576.  256 threads = 8 warps.
// Warp tile: 16 px x 64 o.  3 split terms: xh*wh + xl*wh + xh*wl.
// Dynamic smem = 49152 B exactly; ZERO static smem (bias via __ldg) so the
// launch stays under the 48 KB no-opt-in ceiling:
//   XH [128px][64c] bf16 swz @0      (16384)
//   XL                       @16384  (16384)
//   WH [64o][64c] bf16 swz   @32768  ( 8192)
//   WL                       @40960  ( 8192)
// ===========================================================================
#define SM_XH  0
#define SM_XL  16384
#define SM_WH  32768
#define SM_WL  40960
#define SM_TOT 49152
#define OSTR   132   // s_out row stride in floats (bank-conflict-free pad)

__global__ __launch_bounds__(256, 2) void deform_gemm_kernel(
    const float* __restrict__ x, const float* __restrict__ b_def,
    float* __restrict__ out) {
    extern __shared__ char smem[];
    const uint32_t sbase = smem_to_u32(smem);

    int t    = threadIdx.x;
    int wid  = t >> 5;
    int lane = t & 31;
    int blk  = blockIdx.x;
    int h    = blk & (H_ - 1);
    int b    = blk >> 7;

    const float* xb = x + (size_t)b * C_ * HW_;
    const int sp = t & 127;        // sampled pixel (w coordinate)
    const int cg = (t >> 7) * 32;  // channel half

    // ldmatrix lane-pattern byte offsets (tile-local, pre-swizzle)
    const int wb = wid * 16;
    const uint32_t aRowOff = (uint32_t)((wb + (lane & 15)) * 128 +
                                        ((lane >> 4) & 1) * 16);
    const uint32_t bRowOff = (uint32_t)((((lane & 7) + ((lane >> 4) & 1) * 8)) * 128 +
                                        ((lane >> 3) & 1) * 16);

    float acc[8][4] = {};   // [ntile(8 o's each)][frag]

    for (int k = 0; k < K2_; k++) {
        // ---- per-pixel bilinear setup (registers) ----
        int dy = k / 3 - 1;
        int dx = k % 3 - 1;
        int obase = (b * OCOFF * H_ + h) * W_ + sp;
        float ox = g_off[obase + (0 * 9 + k) * HW_];
        float oy = g_off[obase + (1 * 9 + k) * HW_];
        float m  = g_off[obase + (2 * 9 + k) * HW_];
        float ys = (float)(h + dy) + oy;
        float xs = (float)(sp + dx) + ox;
        float y0f = floorf(ys);
        float x0f = floorf(xs);
        float wy1 = ys - y0f;
        float wx1 = xs - x0f;
        int y0 = (int)y0f;
        int x0 = (int)x0f;
        int   iv[4];
        float wf[4];
#pragma unroll
        for (int cr = 0; cr < 4; cr++) {
            int oyc = cr >> 1;
            int oxc = cr & 1;
            int yy = y0 + oyc;
            int xx = x0 + oxc;
            float wgt = (oyc ? wy1 : 1.f - wy1) * (oxc ? wx1 : 1.f - wx1) * m;
            bool valid = (yy >= 0) && (yy < H_) && (xx >= 0) && (xx < W_);
            int yc = min(max(yy, 0), H_ - 1);
            int xc = min(max(xx, 0), W_ - 1);
            iv[cr] = yc * W_ + xc;
            wf[cr] = valid ? wgt : 0.f;
        }
        // ---- sample 32 channels for pixel sp, hi/lo split, swizzled stores ----
#pragma unroll
        for (int q = 0; q < 4; q++) {
            int c0 = cg + q * 8;
            float v[8];
#pragma unroll
            for (int j = 0; j < 8; j++) {
                const float* xc = xb + (c0 + j) * HW_;
                v[j] = wf[0] * __ldg(xc + iv[0]) + wf[1] * __ldg(xc + iv[1]) +
                       wf[2] * __ldg(xc + iv[2]) + wf[3] * __ldg(xc + iv[3]);
            }
            uint32_t hi[4];
            uint32_t lo[4];
#pragma unroll
            for (int mm = 0; mm < 4; mm++) {
                float a0 = v[2 * mm];
                float a1 = v[2 * mm + 1];
                __nv_bfloat16 h0 = __float2bfloat16(a0);
                __nv_bfloat16 h1 = __float2bfloat16(a1);
                __nv_bfloat16 l0 = __float2bfloat16(a0 - __bfloat162float(h0));
                __nv_bfloat16 l1 = __float2bfloat16(a1 - __bfloat162float(h1));
                hi[mm] = (uint32_t)__bfloat16_as_ushort(h0) |
                         ((uint32_t)__bfloat16_as_ushort(h1) << 16);
                lo[mm] = (uint32_t)__bfloat16_as_ushort(l0) |
                         ((uint32_t)__bfloat16_as_ushort(l1) << 16);
            }
            uint32_t so = SWZ((uint32_t)(sp * 128 + c0 * 2));
            *(uint4*)(smem + SM_XH + so) = make_uint4(hi[0], hi[1], hi[2], hi[3]);
            *(uint4*)(smem + SM_XL + so) = make_uint4(lo[0], lo[1], lo[2], lo[3]);
        }
        // ---- stage pre-swizzled weight tiles (straight float4 copies) ----
        {
            int i0 = t;
            int i1 = t + 256;
            ((float4*)(smem + SM_WH))[i0] = ((const float4*)(g_wbh + k * 4096))[i0];
            ((float4*)(smem + SM_WH))[i1] = ((const float4*)(g_wbh + k * 4096))[i1];
            ((float4*)(smem + SM_WL))[i0] = ((const float4*)(g_wbl + k * 4096))[i0];
            ((float4*)(smem + SM_WL))[i1] = ((const float4*)(g_wbl + k * 4096))[i1];
        }
        __syncthreads();
        // ---- GEMM: ldmatrix + mma.sync, 3 split terms ----
#pragma unroll
        for (int kc = 0; kc < 4; kc++) {
            uint32_t ah[4], al[4];
            uint32_t aoff = SWZ(aRowOff + kc * 32);
            LDSM_X4(ah, sbase + SM_XH + aoff);
            LDSM_X4(al, sbase + SM_XL + aoff);
#pragma unroll
            for (int nt = 0; nt < 4; nt++) {
                uint32_t bh[4], bl[4];
                uint32_t boff = SWZ(bRowOff + (uint32_t)(nt * 16 * 128 + kc * 32));
                LDSM_X4(bh, sbase + SM_WH + boff);
                LDSM_X4(bl, sbase + SM_WL + boff);
                MMA_BF16(acc[nt * 2],     ah, bh[0], bh[1]);
                MMA_BF16(acc[nt * 2],     al, bh[0], bh[1]);
                MMA_BF16(acc[nt * 2],     ah, bl[0], bl[1]);
                MMA_BF16(acc[nt * 2 + 1], ah, bh[2], bh[3]);
                MMA_BF16(acc[nt * 2 + 1], al, bh[2], bh[3]);
                MMA_BF16(acc[nt * 2 + 1], ah, bl[2], bl[3]);
            }
        }
        __syncthreads();
    }

    // ---- epilogue: fragments -> padded smem [o][OSTR] -> coalesced STG ----
    float* s_out = (float*)smem;   // 64 * 132 * 4 = 33792 B (reuses XH/XL/WH)
    {
        int prow = wb + (lane >> 2);
#pragma unroll
        for (int nt2 = 0; nt2 < 8; nt2++) {
            int o0 = nt2 * 8 + 2 * (lane & 3);
            float b0 = __ldg(b_def + o0);
            float b1 = __ldg(b_def + o0 + 1);
            s_out[o0 * OSTR + prow]           = fmaxf(acc[nt2][0] + b0, 0.f);
            s_out[(o0 + 1) * OSTR + prow]     = fmaxf(acc[nt2][1] + b1, 0.f);
            s_out[o0 * OSTR + prow + 8]       = fmaxf(acc[nt2][2] + b0, 0.f);
            s_out[(o0 + 1) * OSTR + prow + 8] = fmaxf(acc[nt2][3] + b1, 0.f);
        }
    }
    __syncthreads();
    for (int i = t; i < 2048; i += 256) {
        int o  = i >> 5;
        int pq = i & 31;
        float4 vv = *(const float4*)&s_out[o * OSTR + pq * 4];
        *(float4*)&out[(((size_t)b * O_ + o) * H_ + h) * W_ + pq * 4] = vv;
    }
}

// ===========================================================================
extern "C" void kernel_launch(void* const* d_in, const int* in_sizes, int n_in,
                              void* d_out, int out_size) {
    const float* x     = (const float*)d_in[0];
    const float* feat  = (const float*)d_in[1];
    const float* w_off = (const float*)d_in[2];
    const float* b_off = (const float*)d_in[3];
    const float* w_def = (const float*)d_in[4];
    const float* b_def = (const float*)d_in[5];
    float* out = (float*)d_out;

    prep_w_kernel<<<(K2_ * O_ * C_ + 255) / 256, 256>>>(w_off, w_def);
    offset_conv_kernel<<<B_ * H_ * (W_ / 64), 256>>>(feat, b_off);
    deform_gemm_kernel<<<B_ * H_, 256, SM_TOT>>>(x, b_def, out);
}